// round 1
// baseline (speedup 1.0000x reference)
#include <cuda_runtime.h>

#define N_NODES 50000
#define N_EDGES 800000
#define F 128

// ---- device scratch (no allocs allowed) ----
__device__ float g_h[N_NODES * F];        // h = feat @ Wp^T + bp
__device__ float g_wsum[N_NODES];
__device__ int   g_cnt[N_NODES];
__device__ int   g_rowptr[N_NODES + 1];
__device__ int   g_cursor[N_NODES];
__device__ int   g_ssrc[N_EDGES];         // src sorted by dst
__device__ float g_sm[N_EDGES];           // m  sorted by dst

typedef unsigned long long u64;

__device__ __forceinline__ u64 fma2(u64 a, u64 b, u64 c) {
    u64 d;
    asm("fma.rn.f32x2 %0, %1, %2, %3;" : "=l"(d) : "l"(a), "l"(b), "l"(c));
    return d;
}
__device__ __forceinline__ u64 splat2(float x) {
    u64 d; unsigned xi = __float_as_uint(x);
    asm("mov.b64 %0, {%1, %1};" : "=l"(d) : "r"(xi));
    return d;
}

// ---- K1: zero accumulators ----
__global__ void k_init() {
    int i = blockIdx.x * blockDim.x + threadIdx.x;
    if (i < N_NODES) { g_wsum[i] = 0.f; g_cnt[i] = 0; }
}

// ---- K2: per-dst edge count + weight sum ----
__global__ void k_count(const float* __restrict__ efeat, const int* __restrict__ dst) {
    int e = blockIdx.x * blockDim.x + threadIdx.x;
    if (e < N_EDGES) {
        int d = dst[e];
        atomicAdd(&g_wsum[d], efeat[e]);
        atomicAdd(&g_cnt[d], 1);
    }
}

// ---- K3: exclusive scan of counts -> rowptr, cursor (single block, shuffle-based) ----
__global__ void k_scan() {
    __shared__ int wsums[32];
    __shared__ int s_total;
    int t = threadIdx.x, lane = t & 31, wid = t >> 5;
    int carry = 0;
    for (int base = 0; base < N_NODES; base += 4096) {
        int i0 = base + t * 4;
        int x0 = 0, x1 = 0, x2 = 0, x3 = 0;
        if (i0 + 3 < N_NODES) {
            int4 v = *(const int4*)&g_cnt[i0];
            x0 = v.x; x1 = v.y; x2 = v.z; x3 = v.w;
        } else {
            if (i0 + 0 < N_NODES) x0 = g_cnt[i0 + 0];
            if (i0 + 1 < N_NODES) x1 = g_cnt[i0 + 1];
            if (i0 + 2 < N_NODES) x2 = g_cnt[i0 + 2];
            if (i0 + 3 < N_NODES) x3 = g_cnt[i0 + 3];
        }
        int s1 = x0, s2 = s1 + x1, s3 = s2 + x2, s4 = s3 + x3;
        // warp inclusive scan of per-thread sums
        int v = s4;
        #pragma unroll
        for (int off = 1; off < 32; off <<= 1) {
            int u = __shfl_up_sync(0xffffffffu, v, off);
            if (lane >= off) v += u;
        }
        int warp_excl = v - s4;
        if (lane == 31) wsums[wid] = v;
        __syncthreads();
        if (t < 32) {
            int wv = wsums[t];
            int vv = wv;
            #pragma unroll
            for (int off = 1; off < 32; off <<= 1) {
                int u = __shfl_up_sync(0xffffffffu, vv, off);
                if (t >= off) vv += u;
            }
            wsums[t] = vv - wv;            // exclusive warp offset
            if (t == 31) s_total = vv;     // chunk total
        }
        __syncthreads();
        int bofs = carry + wsums[wid] + warp_excl;
        if (i0 + 0 < N_NODES) { g_rowptr[i0 + 0] = bofs;      g_cursor[i0 + 0] = bofs;      }
        if (i0 + 1 < N_NODES) { g_rowptr[i0 + 1] = bofs + s1; g_cursor[i0 + 1] = bofs + s1; }
        if (i0 + 2 < N_NODES) { g_rowptr[i0 + 2] = bofs + s2; g_cursor[i0 + 2] = bofs + s2; }
        if (i0 + 3 < N_NODES) { g_rowptr[i0 + 3] = bofs + s3; g_cursor[i0 + 3] = bofs + s3; }
        carry += s_total;
        __syncthreads();   // protect wsums/s_total for next chunk
    }
    if (t == 0) g_rowptr[N_NODES] = carry;
}

// ---- K4: scatter edges into CSR order; compute m = exp(-w/wsum[dst]) on the fly ----
__global__ void k_scatter(const float* __restrict__ efeat, const int* __restrict__ src,
                          const int* __restrict__ dst) {
    int e = blockIdx.x * blockDim.x + threadIdx.x;
    if (e < N_EDGES) {
        int d = dst[e];
        float w = efeat[e];
        float m = expf(-w / g_wsum[d]);
        int pos = atomicAdd(&g_cursor[d], 1);
        g_ssrc[pos] = src[e];
        g_sm[pos] = m;
    }
}

// ---- K5: fused dual GEMM: g_h = feat@Wp^T + bp, out = feat@Ws^T + bs ----
// block = 256 threads, tile = 64 rows x 128 cols. f32x2 packed FMA along M.
#define GEMM_SMEM (128 * 64 * 4 + 128 * 129 * 4)

__device__ __forceinline__ void load_W(float* sW, const float* __restrict__ W, int t) {
    #pragma unroll
    for (int it = 0; it < 16; ++it) {
        int fidx = (it * 256 + t) * 4;
        int n = fidx >> 7, k = fidx & 127;
        float4 v = *(const float4*)&W[fidx];
        sW[n * 129 + k + 0] = v.x;
        sW[n * 129 + k + 1] = v.y;
        sW[n * 129 + k + 2] = v.z;
        sW[n * 129 + k + 3] = v.w;
    }
}

__device__ __forceinline__ void compute_pass(const float* sA, const float* sW,
                                             int tx, int ty, u64 acc[4][4]) {
    #pragma unroll 4
    for (int k = 0; k < 128; ++k) {
        const u64* aP = (const u64*)&sA[k * 64 + ty * 8];
        u64 a0 = aP[0], a1 = aP[1], a2 = aP[2], a3 = aP[3];
        #pragma unroll
        for (int j = 0; j < 4; ++j) {
            u64 b2 = splat2(sW[(tx + 32 * j) * 129 + k]);
            acc[0][j] = fma2(a0, b2, acc[0][j]);
            acc[1][j] = fma2(a1, b2, acc[1][j]);
            acc[2][j] = fma2(a2, b2, acc[2][j]);
            acc[3][j] = fma2(a3, b2, acc[3][j]);
        }
    }
}

__device__ __forceinline__ void epilogue(u64 acc[4][4], const float* __restrict__ bias,
                                         float* __restrict__ dstp, int m0, int tx, int ty) {
    int mbase = m0 + ty * 8;
    #pragma unroll
    for (int j = 0; j < 4; ++j) {
        int n = tx + 32 * j;
        float bb = bias[n];
        #pragma unroll
        for (int i2 = 0; i2 < 4; ++i2) {
            u64 a = acc[i2][j];
            float lo = __uint_as_float((unsigned)(a & 0xffffffffu));
            float hi = __uint_as_float((unsigned)(a >> 32));
            int r0 = mbase + 2 * i2;
            if (r0 < N_NODES)     dstp[(long)r0 * F + n]       = lo + bb;
            if (r0 + 1 < N_NODES) dstp[(long)(r0 + 1) * F + n] = hi + bb;
        }
    }
}

__global__ void k_gemm(const float* __restrict__ feat,
                       const float* __restrict__ Wp, const float* __restrict__ bp,
                       const float* __restrict__ Ws, const float* __restrict__ bs,
                       float* __restrict__ out) {
    extern __shared__ float smem[];
    float* sA = smem;               // [k][m] transposed: sA[k*64+m]
    float* sW = smem + 128 * 64;    // [n][129]
    int t = threadIdx.x;
    int m0 = blockIdx.x * 64;
    int tx = t & 31, ty = t >> 5;

    // load A tile transposed (pairs along M contiguous -> LDS.64 in compute)
    {
        int m = t & 63;
        int kb = (t >> 6) << 2;
        int gm = m0 + m;
        #pragma unroll
        for (int it = 0; it < 8; ++it) {
            int k4 = kb + it * 16;
            float4 v = make_float4(0.f, 0.f, 0.f, 0.f);
            if (gm < N_NODES) v = *(const float4*)&feat[(long)gm * F + k4];
            sA[(k4 + 0) * 64 + m] = v.x;
            sA[(k4 + 1) * 64 + m] = v.y;
            sA[(k4 + 2) * 64 + m] = v.z;
            sA[(k4 + 3) * 64 + m] = v.w;
        }
    }
    load_W(sW, Wp, t);
    __syncthreads();

    u64 acc[4][4];
    #pragma unroll
    for (int i = 0; i < 4; ++i)
        #pragma unroll
        for (int j = 0; j < 4; ++j) acc[i][j] = 0ull;

    compute_pass(sA, sW, tx, ty, acc);
    epilogue(acc, bp, g_h, m0, tx, ty);
    __syncthreads();

    load_W(sW, Ws, t);
    __syncthreads();

    #pragma unroll
    for (int i = 0; i < 4; ++i)
        #pragma unroll
        for (int j = 0; j < 4; ++j) acc[i][j] = 0ull;

    compute_pass(sA, sW, tx, ty, acc);
    epilogue(acc, bs, out, m0, tx, ty);
}

// ---- K6: warp-per-node CSR aggregation; out += (sum m*h[src]) / max(deg,1) ----
__global__ void k_agg(float* __restrict__ out) {
    int node = (blockIdx.x * blockDim.x + threadIdx.x) >> 5;
    int lane = threadIdx.x & 31;
    if (node >= N_NODES) return;
    int beg = g_rowptr[node], end = g_rowptr[node + 1];

    float4 acc = make_float4(0.f, 0.f, 0.f, 0.f);
    for (int e0 = beg; e0 < end; e0 += 32) {
        int i = e0 + lane;
        int s = 0; float mv = 0.f;
        if (i < end) { s = g_ssrc[i]; mv = g_sm[i]; }
        int cnt = min(32, end - e0);
        for (int j = 0; j < cnt; ++j) {
            int ss = __shfl_sync(0xffffffffu, s, j);
            float mm = __shfl_sync(0xffffffffu, mv, j);
            float4 hv = *(const float4*)&g_h[(long)ss * F + lane * 4];
            acc.x += mm * hv.x;
            acc.y += mm * hv.y;
            acc.z += mm * hv.z;
            acc.w += mm * hv.w;
        }
    }
    int deg = end - beg;
    float inv = 1.0f / (float)(deg > 1 ? deg : 1);
    float4* po = (float4*)&out[(long)node * F + lane * 4];
    float4 o = *po;
    o.x += acc.x * inv;
    o.y += acc.y * inv;
    o.z += acc.z * inv;
    o.w += acc.w * inv;
    *po = o;
}

extern "C" void kernel_launch(void* const* d_in, const int* in_sizes, int n_in,
                              void* d_out, int out_size) {
    const float* feat  = (const float*)d_in[0];
    const float* efeat = (const float*)d_in[1];
    const int*   src   = (const int*)d_in[2];
    const int*   dst   = (const int*)d_in[3];
    const float* Wp    = (const float*)d_in[4];
    const float* bp    = (const float*)d_in[5];
    const float* Ws    = (const float*)d_in[6];
    const float* bs    = (const float*)d_in[7];
    float* out = (float*)d_out;

    cudaFuncSetAttribute(k_gemm, cudaFuncAttributeMaxDynamicSharedMemorySize, GEMM_SMEM);

    k_init<<<(N_NODES + 255) / 256, 256>>>();
    k_count<<<(N_EDGES + 255) / 256, 256>>>(efeat, dst);
    k_scan<<<1, 1024>>>();
    k_scatter<<<(N_EDGES + 255) / 256, 256>>>(efeat, src, dst);
    k_gemm<<<(N_NODES + 63) / 64, 256, GEMM_SMEM>>>(feat, Wp, bp, Ws, bs, out);
    k_agg<<<(N_NODES * 32 + 255) / 256, 256>>>(out);
}